// round 6
// baseline (speedup 1.0000x reference)
#include <cuda_runtime.h>

#define B_   256
#define R_   1152
#define C_   10
#define IC_  8
#define OC_  16
#define RT_  16
#define CHUNKS_ (R_/RT_)   /* 72 */
#define NG_   (B_*C_*OC_)  /* 40960 */

// Scratch (static device memory — no allocations).
__device__ __align__(16) float g_Vsum[NG_];             // running sum of v_j
__device__ __align__(16) float g_scratch[CHUNKS_*NG_];  // per-r-chunk partial s

// ---- packed fp32x2 helpers (Blackwell FFMA2 — only reachable via PTX) ------
__device__ __forceinline__ unsigned long long fma2(unsigned long long a,
                                                   unsigned long long b,
                                                   unsigned long long c) {
    unsigned long long d;
    asm("fma.rn.f32x2 %0, %1, %2, %3;" : "=l"(d) : "l"(a), "l"(b), "l"(c));
    return d;
}
__device__ __forceinline__ unsigned long long bcast2(float x) {
    unsigned long long d; unsigned int u = __float_as_uint(x);
    asm("mov.b64 %0, {%1, %1};" : "=l"(d) : "r"(u));
    return d;
}
__device__ __forceinline__ float2 unpack2(unsigned long long v) {
    unsigned int lo, hi;
    asm("mov.b64 {%0, %1}, %2;" : "=r"(lo), "=r"(hi) : "l"(v));
    return make_float2(__uint_as_float(lo), __uint_as_float(hi));
}

// ---------------------------------------------------------------------------
// First routing pass (uniform coupling 0.1): nb=2, osplit=4, packed f32x2.
// Grid (CHUNKS_, 2), block 256. Thread -> (batch pair, o-quarter).
// ---------------------------------------------------------------------------
__global__ __launch_bounds__(256, 1)
void pass_first(const float* __restrict__ x, const float* __restrict__ w) {
    extern __shared__ float4 Ws[];            // [RT_][C_][IC_][4] float4 = 80 KB
    const int tid   = threadIdx.x;
    const int chunk = blockIdx.x;
    const int r0    = chunk * RT_;
    const int oq    = tid & 3;
    const int b0    = blockIdx.y * 128 + (tid >> 2) * 2;

    const float4* wsrc = reinterpret_cast<const float4*>(w) + (size_t)r0 * (C_*IC_*4);
    #pragma unroll
    for (int k = 0; k < (RT_*C_*IC_*4)/256; ++k) Ws[k*256 + tid] = wsrc[k*256 + tid];
    __syncthreads();

    unsigned long long s0[C_][2], s1[C_][2];
    #pragma unroll
    for (int c = 0; c < C_; ++c) {
        s0[c][0] = 0ull; s0[c][1] = 0ull;
        s1[c][0] = 0ull; s1[c][1] = 0ull;
    }

    const float* xrow0 = x + ((size_t)b0       * R_ + r0) * IC_;
    const float* xrow1 = x + ((size_t)(b0 + 1) * R_ + r0) * IC_;

    #pragma unroll 1
    for (int r = 0; r < RT_; ++r) {
        float4 xa = *reinterpret_cast<const float4*>(xrow0 + r*IC_);
        float4 xb = *reinterpret_cast<const float4*>(xrow0 + r*IC_ + 4);
        float4 ya = *reinterpret_cast<const float4*>(xrow1 + r*IC_);
        float4 yb = *reinterpret_cast<const float4*>(xrow1 + r*IC_ + 4);
        unsigned long long x2[8], y2[8];
        x2[0]=bcast2(xa.x); x2[1]=bcast2(xa.y); x2[2]=bcast2(xa.z); x2[3]=bcast2(xa.w);
        x2[4]=bcast2(xb.x); x2[5]=bcast2(xb.y); x2[6]=bcast2(xb.z); x2[7]=bcast2(xb.w);
        y2[0]=bcast2(ya.x); y2[1]=bcast2(ya.y); y2[2]=bcast2(ya.z); y2[3]=bcast2(ya.w);
        y2[4]=bcast2(yb.x); y2[5]=bcast2(yb.y); y2[6]=bcast2(yb.z); y2[7]=bcast2(yb.w);

        const ulonglong2* wr2 =
            reinterpret_cast<const ulonglong2*>(Ws) + (size_t)r * (C_*IC_*4) + oq;
        #pragma unroll
        for (int c = 0; c < C_; ++c) {
            #pragma unroll
            for (int i = 0; i < IC_; ++i) {
                ulonglong2 q = wr2[(c*IC_ + i)*4];        // 16B smem broadcast
                s0[c][0] = fma2(x2[i], q.x, s0[c][0]);
                s0[c][1] = fma2(x2[i], q.y, s0[c][1]);
                s1[c][0] = fma2(y2[i], q.x, s1[c][0]);
                s1[c][1] = fma2(y2[i], q.y, s1[c][1]);
            }
        }
    }

    float* dst0 = g_scratch + ((size_t)chunk * B_ +  b0     ) * (C_*OC_) + oq * 4;
    float* dst1 = g_scratch + ((size_t)chunk * B_ + (b0 + 1)) * (C_*OC_) + oq * 4;
    #pragma unroll
    for (int c = 0; c < C_; ++c) {
        float2 a0 = unpack2(s0[c][0]), a1 = unpack2(s0[c][1]);
        float2 d0 = unpack2(s1[c][0]), d1 = unpack2(s1[c][1]);
        *reinterpret_cast<float4*>(dst0 + c*OC_) =
            make_float4(a0.x*0.1f, a0.y*0.1f, a1.x*0.1f, a1.y*0.1f);
        *reinterpret_cast<float4*>(dst1 + c*OC_) =
            make_float4(d0.x*0.1f, d0.y*0.1f, d1.x*0.1f, d1.y*0.1f);
    }
}

// ---------------------------------------------------------------------------
// Routing iteration pass: nb=1, osplit=2, packed f32x2 throughout.
// Grid (CHUNKS_, 2), block 256. Thread -> (b = by*128 + tid/2, o-half = tid&1).
// ---------------------------------------------------------------------------
__global__ __launch_bounds__(256, 1)
void pass_iter(const float* __restrict__ x, const float* __restrict__ w) {
    extern __shared__ float4 Ws[];            // 80 KB
    const int tid   = threadIdx.x;
    const int chunk = blockIdx.x;
    const int r0    = chunk * RT_;
    const int oh    = tid & 1;
    const int b     = blockIdx.y * 128 + (tid >> 1);

    const float4* wsrc = reinterpret_cast<const float4*>(w) + (size_t)r0 * (C_*IC_*4);
    #pragma unroll
    for (int k = 0; k < (RT_*C_*IC_*4)/256; ++k) Ws[k*256 + tid] = wsrc[k*256 + tid];
    __syncthreads();

    unsigned long long s2[C_][4];
    #pragma unroll
    for (int c = 0; c < C_; ++c)
        #pragma unroll
        for (int j = 0; j < 4; ++j) s2[c][j] = 0ull;

    const float* xrow = x + ((size_t)b * R_ + r0) * IC_;
    const ulonglong2* vs2 =
        reinterpret_cast<const ulonglong2*>(g_Vsum + b * (C_*OC_) + oh * 8);

    #pragma unroll 1
    for (int r = 0; r < RT_; ++r) {
        float4 xa = *reinterpret_cast<const float4*>(xrow + r*IC_);
        float4 xb = *reinterpret_cast<const float4*>(xrow + r*IC_ + 4);
        unsigned long long x2[8];
        x2[0]=bcast2(xa.x); x2[1]=bcast2(xa.y); x2[2]=bcast2(xa.z); x2[3]=bcast2(xa.w);
        x2[4]=bcast2(xb.x); x2[5]=bcast2(xb.y); x2[6]=bcast2(xb.z); x2[7]=bcast2(xb.w);

        const ulonglong2* wr2 =
            reinterpret_cast<const ulonglong2*>(Ws) + (size_t)r * (C_*IC_*4) + oh*2;

        unsigned long long u2[C_][4];
        float t[C_];
        #pragma unroll
        for (int c = 0; c < C_; ++c) {
            unsigned long long a0=0ull, a1=0ull, a2=0ull, a3=0ull;
            #pragma unroll
            for (int i = 0; i < IC_; ++i) {
                ulonglong2 pA = wr2[(c*IC_ + i)*4];       // 16B smem broadcast
                ulonglong2 pB = wr2[(c*IC_ + i)*4 + 1];
                a0 = fma2(x2[i], pA.x, a0);
                a1 = fma2(x2[i], pA.y, a1);
                a2 = fma2(x2[i], pB.x, a2);
                a3 = fma2(x2[i], pB.y, a3);
            }
            u2[c][0]=a0; u2[c][1]=a1; u2[c][2]=a2; u2[c][3]=a3;
            ulonglong2 vA = vs2[c*4];                     // L1-hit
            ulonglong2 vB = vs2[c*4 + 1];
            unsigned long long t2 = 0ull;
            t2 = fma2(a0, vA.x, t2);
            t2 = fma2(a1, vA.y, t2);
            t2 = fma2(a2, vB.x, t2);
            t2 = fma2(a3, vB.y, t2);
            float2 tp = unpack2(t2);
            t[c] = tp.x + tp.y;
        }

        // partner lane (same b, other o-half) completes the dot product
        #pragma unroll
        for (int c = 0; c < C_; ++c) t[c] += __shfl_xor_sync(0xffffffffu, t[c], 1);
        float m = t[0];
        #pragma unroll
        for (int c = 1; c < C_; ++c) m = fmaxf(m, t[c]);
        float z = 0.0f;
        #pragma unroll
        for (int c = 0; c < C_; ++c) { t[c] = __expf(t[c] - m); z += t[c]; }
        float inv = __fdividef(1.0f, z);

        #pragma unroll
        for (int c = 0; c < C_; ++c) {
            unsigned long long cc2 = bcast2(t[c] * inv);
            s2[c][0] = fma2(cc2, u2[c][0], s2[c][0]);
            s2[c][1] = fma2(cc2, u2[c][1], s2[c][1]);
            s2[c][2] = fma2(cc2, u2[c][2], s2[c][2]);
            s2[c][3] = fma2(cc2, u2[c][3], s2[c][3]);
        }
    }

    float* dst = g_scratch + ((size_t)chunk * B_ + b) * (C_*OC_) + oh * 8;
    #pragma unroll
    for (int c = 0; c < C_; ++c) {
        float2 e0 = unpack2(s2[c][0]), e1 = unpack2(s2[c][1]);
        float2 e2 = unpack2(s2[c][2]), e3 = unpack2(s2[c][3]);
        *reinterpret_cast<float4*>(dst + c*OC_) =
            make_float4(e0.x, e0.y, e1.x, e1.y);
        *reinterpret_cast<float4*>(dst + c*OC_ + 4) =
            make_float4(e2.x, e2.y, e3.x, e3.y);
    }
}

// ---------------------------------------------------------------------------
// Reduce 72 partials, squash, update Vsum / emit output.
// Block 256 = 32 g-float4 x 8 k-slices (9 float4 loads each), smem combine,
// 4-lane shfl squash on the first 32 threads. Grid 320.
// ---------------------------------------------------------------------------
template<bool FIRSTV, bool LAST>
__global__ __launch_bounds__(256, 4)
void squash_kernel(float* __restrict__ out) {
    const int tid = threadIdx.x;
    const int ks  = tid >> 5;          // 0..7
    const int gl  = tid & 31;          // 0..31
    const int g4  = blockIdx.x * 32 + gl;   // float4 index into [NG_/4]

    const float4* src = reinterpret_cast<const float4*>(g_scratch);
    float4 a = make_float4(0.f, 0.f, 0.f, 0.f);
    #pragma unroll
    for (int k = 0; k < CHUNKS_/8; ++k) {
        float4 tv = src[(size_t)(ks * (CHUNKS_/8) + k) * (NG_/4) + g4];
        a.x += tv.x; a.y += tv.y; a.z += tv.z; a.w += tv.w;
    }

    __shared__ float4 red[8][32];
    red[ks][gl] = a;
    __syncthreads();

    if (tid < 32) {
        float4 s = red[0][tid];
        #pragma unroll
        for (int j = 1; j < 8; ++j) {
            float4 t = red[j][tid];
            s.x += t.x; s.y += t.y; s.z += t.z; s.w += t.w;
        }
        float sq = s.x*s.x + s.y*s.y + s.z*s.z + s.w*s.w;
        sq += __shfl_xor_sync(0xffffffffu, sq, 1);      // 4 float4 lanes = one
        sq += __shfl_xor_sync(0xffffffffu, sq, 2);      // (b,c) 16-vector
        float n = sqrtf(sq);
        float sc = (sq / (1.0f + sq)) / (n + 1e-8f);
        float4 v = make_float4(s.x*sc, s.y*sc, s.z*sc, s.w*sc);
        int g = blockIdx.x * 32 + tid;
        if (LAST) {
            reinterpret_cast<float4*>(out)[g] = v;
        } else if (FIRSTV) {
            reinterpret_cast<float4*>(g_Vsum)[g] = v;
        } else {
            float4 o = reinterpret_cast<float4*>(g_Vsum)[g];
            o.x += v.x; o.y += v.y; o.z += v.z; o.w += v.w;
            reinterpret_cast<float4*>(g_Vsum)[g] = o;
        }
    }
}

extern "C" void kernel_launch(void* const* d_in, const int* in_sizes, int n_in,
                              void* d_out, int out_size) {
    const float* x = (const float*)d_in[0];
    const float* w = (const float*)d_in[1];
    float* out = (float*)d_out;

    const size_t smem = (size_t)RT_ * C_ * IC_ * 4 * sizeof(float4);  // 81920 B
    cudaFuncSetAttribute(pass_first, cudaFuncAttributeMaxDynamicSharedMemorySize, (int)smem);
    cudaFuncSetAttribute(pass_iter,  cudaFuncAttributeMaxDynamicSharedMemorySize, (int)smem);

    dim3 grid(CHUNKS_, 2);

    pass_first<<<grid, 256, smem>>>(x, w);           // iter 1 (uniform coupling)
    squash_kernel<true,  false><<<320, 256>>>(out);  // v1, Vsum = v1
    pass_iter<<<grid, 256, smem>>>(x, w);            // iter 2
    squash_kernel<false, false><<<320, 256>>>(out);  // v2, Vsum = v1+v2
    pass_iter<<<grid, 256, smem>>>(x, w);            // iter 3
    squash_kernel<false, true ><<<320, 256>>>(out);  // v3 -> output
}